// round 2
// baseline (speedup 1.0000x reference)
#include <cuda_runtime.h>
#include <cuda_bf16.h>

#define N_NODES 100000
#define DEG 16
#define N_EDGES (N_NODES * DEG)
#define D_FEAT 64

// Allocation-free scratch: ping-pong feature buffers + normalized int32 indices.
__device__ float g_buf0[N_NODES * D_FEAT];
__device__ float g_buf1[N_NODES * D_FEAT];
__device__ int   g_indices[N_EDGES];

// Normalize indices to int32 regardless of whether the harness delivered them
// as int64 (reference dtype) or already converted to int32.
// Detection: if int64 little-endian, the odd 32-bit words are the high halves
// and are all zero (indices < 100000). If int32, odd words are random indices;
// the probability 64 consecutive ones are all zero is ~1e-320.
__global__ void convert_indices_kernel(const int* __restrict__ raw)
{
    int flag = 0;
    #pragma unroll
    for (int i = 0; i < 64; i++) flag |= raw[2 * i + 1];   // safe: >= 1.6M int32s either way
    const bool is64 = (flag == 0);

    const int e = blockIdx.x * blockDim.x + threadIdx.x;
    if (e < N_EDGES) {
        g_indices[e] = is64 ? raw[2 * e] : raw[e];
    }
}

// One SpMM hop: out[r, :] = sum_{k<16} values[r*16+k] * x[idx[r*16+k], :]
//
// Half-warp (16 lanes) per node; lane owns one float4 chunk (4 of 64 feats).
// Each lane loads ONE (index, value) pair; all 16 edges broadcast via shfl.
// Gather of x[nbr] row = 16 lanes x consecutive float4 = coalesced 256B request.
// 256 thr/block = 16 nodes/block; 6250 blocks = exactly 100000 nodes, no tail.
__global__ __launch_bounds__(256, 8) void spmm_hop_kernel(
    const float* __restrict__ x,
    const float* __restrict__ values,
    float* __restrict__ out)
{
    const int gwarp = (blockIdx.x * blockDim.x + threadIdx.x) >> 5;
    const int lane  = threadIdx.x & 31;
    const int node  = gwarp * 2 + (lane >> 4);   // 2 nodes per warp
    const int chunk = lane & 15;                 // which float4 of the row
    const int half  = lane & 16;                 // shuffle base of this half-warp

    const int   e      = node * DEG + chunk;     // < 1.6M, fits int32
    const int   my_idx = g_indices[e];
    const float my_val = __ldg(&values[e]);

    float4 acc = make_float4(0.f, 0.f, 0.f, 0.f);

    #pragma unroll
    for (int k = 0; k < DEG; k++) {
        const int   nbr = __shfl_sync(0xffffffffu, my_idx, half + k);
        const float v   = __shfl_sync(0xffffffffu, my_val, half + k);
        const float4 xv = __ldg(reinterpret_cast<const float4*>(x) +
                                nbr * (D_FEAT / 4) + chunk);
        acc.x = fmaf(v, xv.x, acc.x);
        acc.y = fmaf(v, xv.y, acc.y);
        acc.z = fmaf(v, xv.z, acc.z);
        acc.w = fmaf(v, xv.w, acc.w);
    }

    reinterpret_cast<float4*>(out)[node * (D_FEAT / 4) + chunk] = acc;
}

extern "C" void kernel_launch(void* const* d_in, const int* in_sizes, int n_in,
                              void* d_out, int out_size)
{
    (void)in_sizes; (void)n_in; (void)out_size;
    const float* x       = (const float*)d_in[0];
    const float* values  = (const float*)d_in[1];
    // d_in[2] = indptr (unused; degree fixed at 16)
    const int*   raw_idx = (const int*)d_in[3];   // int32 view; layout auto-detected
    float*       out     = (float*)d_out;

    float *b0, *b1;
    cudaGetSymbolAddress((void**)&b0, g_buf0);
    cudaGetSymbolAddress((void**)&b1, g_buf1);

    convert_indices_kernel<<<(N_EDGES + 255) / 256, 256>>>(raw_idx);

    const int threads = 256;
    const int blocks  = N_NODES / 16;  // exact

    spmm_hop_kernel<<<blocks, threads>>>(x,  values, b0);
    spmm_hop_kernel<<<blocks, threads>>>(b0, values, b1);
    spmm_hop_kernel<<<blocks, threads>>>(b1, values, out);
}